// round 1
// baseline (speedup 1.0000x reference)
#include <cuda_runtime.h>

// KAN layer: out[n,o] = sum_j w[o,j] * CatmullRom(x[n,j]; coeffs[o,j,0..7]) + bias[o]
// Reformulated as GEMM: out = A[1024,1024] @ B[1024,128] + bias
//   A[n, j*8+k] = basis weight of knot k for sample (n,j)   (built in SMEM per tile)
//   B[j*8+k, o] = weights[o,j] * coeffs[o,j,k]              (built once, 512 KB)

#define D_IN  128
#define D_OUT 128
#define KNOTS 8
#define N_ROWS 1024
#define JK (D_IN * KNOTS)   // 1024

// B in "group-of-4" layout: element (jk, o) lives at [(jk>>2)*512 + o*4 + (jk&3)]
// so a thread reads B[jk..jk+3][o] as one float4, coalesced across lanes (o).
__device__ float g_WC[JK * D_OUT];

__global__ void build_wc_kernel(const float* __restrict__ coeffs,
                                const float* __restrict__ weights) {
    int a = blockIdx.x * blockDim.x + threadIdx.x;   // 0 .. 131071, = output address
    int c  = a & 3;
    int o  = (a >> 2) & (D_OUT - 1);
    int g  = a >> 9;
    int jk = g * 4 + c;
    int j  = jk >> 3;
    int k  = jk & 7;
    g_WC[a] = weights[o * D_IN + j] * coeffs[(o * D_IN + j) * KNOTS + k];
}

__global__ __launch_bounds__(512) void kan_main_kernel(
    const float* __restrict__ x,
    const float* __restrict__ bias,
    float* __restrict__ out) {
    __shared__ float a_s[8][JK];     // 32 KB: dense basis rows for 8 samples

    const int tid = threadIdx.x;
    const int n0  = blockIdx.x * 8;

    // ---- Stage 1: build A tile (8 rows x 1024) -- 1024 spline evals, 2/thread ----
    #pragma unroll
    for (int e = tid; e < 8 * D_IN; e += 512) {
        int nn = e >> 7;          // local row 0..7
        int j  = e & (D_IN - 1);
        float xv = x[(n0 + nn) * D_IN + j];
        float xc = fminf(fmaxf(xv, -1.0f), 1.0f);
        float t  = (xc + 1.0f) * (7.0f / 2.0f);     // h = 2/7
        int idx  = (int)floorf(t);
        idx = min(idx, 6);                           // t >= 0 so no low clamp needed
        float u  = t - (float)idx;
        float u2 = u * u, u3 = u2 * u;
        float b0 = 0.5f * (-u3 + 2.0f * u2 - u);
        float b1 = 0.5f * (3.0f * u3 - 5.0f * u2 + 2.0f);
        float b2 = 0.5f * (-3.0f * u3 + 4.0f * u2 + u);
        float b3 = 0.5f * (u3 - u2);
        int p0 = max(idx - 1, 0);
        int p1 = idx;
        int p2 = idx + 1;
        int p3 = min(idx + 2, 7);
        float v[8];
        #pragma unroll
        for (int k = 0; k < 8; k++) {
            float s = 0.0f;
            s += (k == p0) ? b0 : 0.0f;
            s += (k == p1) ? b1 : 0.0f;
            s += (k == p2) ? b2 : 0.0f;
            s += (k == p3) ? b3 : 0.0f;
            v[k] = s;
        }
        float4* dst = (float4*)&a_s[nn][j * 8];
        dst[0] = make_float4(v[0], v[1], v[2], v[3]);
        dst[1] = make_float4(v[4], v[5], v[6], v[7]);
    }
    __syncthreads();

    // ---- Stage 2: GEMM. thread = (o, row-pair); 256 k-groups of 4 ----
    const int o   = tid & (D_OUT - 1);
    const int sub = tid >> 7;         // 0..3
    const int r0  = sub * 2;
    const int r1  = sub * 2 + 1;

    float acc0 = 0.0f, acc1 = 0.0f;
    const float4* __restrict__ B = (const float4*)g_WC;   // B[g*128 + o]

    #pragma unroll 4
    for (int g = 0; g < JK / 4; g++) {
        float4 b  = B[g * D_OUT + o];                       // coalesced LDG.128 (L2)
        float4 a0 = *(const float4*)&a_s[r0][g * 4];        // broadcast LDS.128
        float4 a1 = *(const float4*)&a_s[r1][g * 4];
        acc0 += a0.x * b.x; acc0 += a0.y * b.y; acc0 += a0.z * b.z; acc0 += a0.w * b.w;
        acc1 += a1.x * b.x; acc1 += a1.y * b.y; acc1 += a1.z * b.z; acc1 += a1.w * b.w;
    }

    float bv = bias[o];
    out[(n0 + r0) * D_OUT + o] = acc0 + bv;
    out[(n0 + r1) * D_OUT + o] = acc1 + bv;
}

extern "C" void kernel_launch(void* const* d_in, const int* in_sizes, int n_in,
                              void* d_out, int out_size) {
    const float* x       = (const float*)d_in[0];   // [1024,128]
    const float* coeffs  = (const float*)d_in[1];   // [128,128,8]
    const float* weights = (const float*)d_in[2];   // [128,128]
    const float* bias    = (const float*)d_in[3];   // [128]
    float* out = (float*)d_out;                     // [1024,128]

    build_wc_kernel<<<(JK * D_OUT) / 512, 512>>>(coeffs, weights);
    kan_main_kernel<<<N_ROWS / 8, 512>>>(x, bias, out);
}

// round 4
// speedup vs baseline: 1.7805x; 1.7805x over previous
#include <cuda_runtime.h>
#include <cstdint>

// KAN layer as GEMM: out[1024,128] = A[1024,1024] @ B[1024,128] + bias
//   A[n, j*8+k] = Catmull-Rom basis weight (built in SMEM per n-tile)
//   B[j*8+k, o] = weights[o,j]*coeffs[o,j,k]  (built once, 512 KB, "group-of-4" layout)
//
// Main kernel: grid (128 n-tiles x 4 o-chunks), 128 threads.
//   warp w (0..3) owns K-quarter [w*256, w*256+256); lane = o within 32-chunk.
//   Each thread: 8 rows x 256 k, accumulating in f32x2 pairs (fma.rn.f32x2).
//   End: SMEM reduction of the 4 K-quarter partials, + bias, store.

#define D_IN  128
#define D_OUT 128
#define KNOTS 8
#define N_ROWS 1024
#define JK (D_IN * KNOTS)          // 1024
#define ROWS_PER_TILE 8
#define O_CHUNK 32
#define KSPLIT 4

typedef unsigned long long u64;

__device__ float g_WC[JK * D_OUT];  // [(k/4)*512 + o*4 + (k%3... k%4)]

__global__ void build_wc_kernel(const float* __restrict__ coeffs,
                                const float* __restrict__ weights) {
    int a = blockIdx.x * blockDim.x + threadIdx.x;   // 0 .. 131071
    int c  = a & 3;
    int o  = (a >> 2) & (D_OUT - 1);
    int g  = a >> 9;
    int jk = g * 4 + c;
    int j  = jk >> 3;
    int k  = jk & 7;
    g_WC[a] = weights[o * D_IN + j] * coeffs[(o * D_IN + j) * KNOTS + k];
}

#define FMA2(d, a, b, c) \
    asm("fma.rn.f32x2 %0, %1, %2, %3;" : "=l"(d) : "l"(a), "l"(b), "l"(c))
#define ADD2(d, a, b) \
    asm("add.rn.f32x2 %0, %1, %2;" : "=l"(d) : "l"(a), "l"(b))

__device__ __forceinline__ float pair_sum(u64 v) {
    float lo = __uint_as_float((unsigned)(v & 0xFFFFFFFFull));
    float hi = __uint_as_float((unsigned)(v >> 32));
    return lo + hi;
}

__global__ __launch_bounds__(128) void kan_main_kernel(
    const float* __restrict__ x,
    const float* __restrict__ bias,
    float* __restrict__ out) {
    __shared__ alignas(16) float a_s[ROWS_PER_TILE * JK];        // 32 KB
    __shared__ float red[(KSPLIT - 1) * ROWS_PER_TILE * O_CHUNK]; // 3 KB

    const int tid   = threadIdx.x;
    const int lane  = tid & 31;          // o within chunk
    const int kq    = tid >> 5;          // K-quarter 0..3 (= warp id)
    const int n0    = blockIdx.x * ROWS_PER_TILE;
    const int obase = blockIdx.y * O_CHUNK;
    const int o     = obase + lane;

    // ---- Stage 1: build basis tile A (8 rows x 1024), 8 evals per thread ----
    #pragma unroll
    for (int e = tid; e < ROWS_PER_TILE * D_IN; e += 128) {
        int nn = e >> 7;
        int j  = e & (D_IN - 1);
        float xv = x[(n0 + nn) * D_IN + j];
        float xc = fminf(fmaxf(xv, -1.0f), 1.0f);
        float t  = (xc + 1.0f) * 3.5f;               // h = 2/7
        int idx  = min((int)floorf(t), 6);
        float u  = t - (float)idx;
        float u2 = u * u, u3 = u2 * u;
        float b0 = 0.5f * (-u3 + 2.0f * u2 - u);
        float b1 = 0.5f * (3.0f * u3 - 5.0f * u2 + 2.0f);
        float b2 = 0.5f * (-3.0f * u3 + 4.0f * u2 + u);
        float b3 = 0.5f * (u3 - u2);
        int p0 = max(idx - 1, 0);
        int p3 = min(idx + 2, 7);
        float v[8];
        #pragma unroll
        for (int k = 0; k < 8; k++) {
            float s = 0.0f;
            s += (k == p0)      ? b0 : 0.0f;
            s += (k == idx)     ? b1 : 0.0f;
            s += (k == idx + 1) ? b2 : 0.0f;
            s += (k == p3)      ? b3 : 0.0f;
            v[k] = s;
        }
        float4* dst = (float4*)&a_s[nn * JK + j * 8];
        dst[0] = make_float4(v[0], v[1], v[2], v[3]);
        dst[1] = make_float4(v[4], v[5], v[6], v[7]);
    }
    __syncthreads();

    // ---- Stage 2: K-quarter GEMM, 8 rows/thread, f32x2 packed over k ----
    const int kg0 = kq * (JK / 4 / KSPLIT);          // 64 groups per quarter
    const ulonglong2* __restrict__ Bp = (const ulonglong2*)g_WC;
    const ulonglong2* __restrict__ Ap = (const ulonglong2*)a_s;

    u64 acc0[ROWS_PER_TILE], acc1[ROWS_PER_TILE];
    #pragma unroll
    for (int r = 0; r < ROWS_PER_TILE; r++) { acc0[r] = 0ull; acc1[r] = 0ull; }

    // Prefetch 2 groups ahead to cover L2 latency.
    ulonglong2 bf0 = Bp[(kg0 + 0) * D_OUT + o];
    ulonglong2 bf1 = Bp[(kg0 + 1) * D_OUT + o];

    #pragma unroll 4
    for (int g = 0; g < 64; g++) {
        ulonglong2 b = bf0;
        bf0 = bf1;
        int gn = (g + 2 < 64) ? (g + 2) : 63;
        bf1 = Bp[(kg0 + gn) * D_OUT + o];

        #pragma unroll
        for (int r = 0; r < ROWS_PER_TILE; r++) {
            ulonglong2 a = Ap[r * (JK / 4) + kg0 + g];   // broadcast LDS.128
            FMA2(acc0[r], a.x, b.x, acc0[r]);
            FMA2(acc1[r], a.y, b.y, acc1[r]);
        }
    }

    // Combine per-row partials to scalars.
    float s[ROWS_PER_TILE];
    #pragma unroll
    for (int r = 0; r < ROWS_PER_TILE; r++) {
        u64 t2;
        ADD2(t2, acc0[r], acc1[r]);
        s[r] = pair_sum(t2);
    }

    // ---- Stage 3: reduce the 4 K-quarter partials in SMEM ----
    if (kq > 0) {
        #pragma unroll
        for (int r = 0; r < ROWS_PER_TILE; r++)
            red[((kq - 1) * ROWS_PER_TILE + r) * O_CHUNK + lane] = s[r];
    }
    __syncthreads();
    if (kq == 0) {
        float bv = bias[o];
        #pragma unroll
        for (int r = 0; r < ROWS_PER_TILE; r++) {
            float v = s[r]
                    + red[(0 * ROWS_PER_TILE + r) * O_CHUNK + lane]
                    + red[(1 * ROWS_PER_TILE + r) * O_CHUNK + lane]
                    + red[(2 * ROWS_PER_TILE + r) * O_CHUNK + lane];
            out[(n0 + r) * D_OUT + o] = v + bv;
        }
    }
}

extern "C" void kernel_launch(void* const* d_in, const int* in_sizes, int n_in,
                              void* d_out, int out_size) {
    const float* x       = (const float*)d_in[0];   // [1024,128]
    const float* coeffs  = (const float*)d_in[1];   // [128,128,8]
    const float* weights = (const float*)d_in[2];   // [128,128]
    const float* bias    = (const float*)d_in[3];   // [128]
    float* out = (float*)d_out;                     // [1024,128]

    build_wc_kernel<<<(JK * D_OUT) / 512, 512>>>(coeffs, weights);
    dim3 grid(N_ROWS / ROWS_PER_TILE, D_OUT / O_CHUNK);   // (128, 4)
    kan_main_kernel<<<grid, 128>>>(x, bias, out);
}